// round 17
// baseline (speedup 1.0000x reference)
#include <cuda_runtime.h>
#include <cuda_bf16.h>
#include <cstdint>
#include <cstddef>

// ---------------------------------------------------------------------------
// DependencyParsingNetwork: embed -> 2-layer biLSTM (T=2048, H=256) -> masked
// tanh score matrix [T,T].
//
//   1. gemm_bias2: 128x128x8 double-buffered tiles, 8x8 register tile.
//   2. lstm_layer: cluster of 8 CTAs per direction. Thread (unit,k) owns
//      K-chunk k for all 4 gates: 8 rotated bank-conflict-free LDS.128,
//      64 FFMA2, width-8 butterfly, lane-split MUFU tanh activations.
//      h exchange: WARP-AGGREGATED st.async.v4.b32 (64 mbarrier arrivals
//      per destination per step instead of 256) + 4-deep mbarrier ring;
//      expect_tx posted 2 steps ahead; no per-step __syncthreads.
//   3..5. second layer + heads + masked MUFU-tanh scores.
// ---------------------------------------------------------------------------

#define TLEN 2048
#define HID  256
#define CSZ  8      // cluster size (CTAs per direction)

// ------------------------- device scratch (static) -------------------------
__device__ float g_pre0f[TLEN * 1024];
__device__ float g_pre0b[TLEN * 1024];
__device__ float g_pre1f[TLEN * 1024];
__device__ float g_pre1b[TLEN * 1024];
__device__ float g_x1[TLEN * 512];
__device__ float g_x2[TLEN * 512];
__device__ float g_sh[TLEN];
__device__ float g_sd[TLEN];

// ------------------------------ helpers ------------------------------------
__device__ __forceinline__ uint32_t smem_u32(const void* p) {
    uint32_t a;
    asm("{ .reg .u64 t; cvta.to.shared.u64 t, %1; cvt.u32.u64 %0, t; }"
        : "=r"(a) : "l"(p));
    return a;
}

#define CLUSTER_SYNC() do { \
    asm volatile("barrier.cluster.arrive.aligned;" ::: "memory"); \
    asm volatile("barrier.cluster.wait.aligned;" ::: "memory"); \
} while (0)

__device__ __forceinline__ void mbar_init(uint32_t mbar, uint32_t count) {
    asm volatile("mbarrier.init.shared.b64 [%0], %1;" :: "r"(mbar), "r"(count)
                 : "memory");
}
__device__ __forceinline__ void mbar_expect_tx(uint32_t mbar, uint32_t bytes) {
    asm volatile("mbarrier.arrive.expect_tx.shared.b64 _, [%0], %1;"
                 :: "r"(mbar), "r"(bytes) : "memory");
}
// acquire at cluster scope: data was produced by remote-CTA st.async
__device__ __forceinline__ void mbar_wait_cluster(uint32_t mbar, uint32_t parity) {
    uint32_t done;
    asm volatile(
        "{\n\t.reg .pred p;\n\t"
        "mbarrier.try_wait.parity.acquire.cluster.shared::cta.b64 p, [%1], %2;\n\t"
        "selp.b32 %0, 1, 0, p;\n\t}"
        : "=r"(done) : "r"(mbar), "r"(parity) : "memory");
    while (!done) {
        asm volatile(
            "{\n\t.reg .pred p;\n\t"
            "mbarrier.try_wait.parity.acquire.cluster.shared::cta.b64 p, [%1], %2, 0x989680;\n\t"
            "selp.b32 %0, 1, 0, p;\n\t}"
            : "=r"(done) : "r"(mbar), "r"(parity) : "memory");
    }
}
__device__ __forceinline__ uint32_t mapa_u32(uint32_t laddr, uint32_t rank) {
    uint32_t r;
    asm volatile("mapa.shared::cluster.u32 %0, %1, %2;"
                 : "=r"(r) : "r"(laddr), "r"(rank));
    return r;
}
// 16-byte remote smem store with tx-count completion on remote mbarrier
__device__ __forceinline__ void st_async_v4(uint32_t raddr,
                                            float a, float b, float c, float d,
                                            uint32_t rbar) {
    asm volatile(
        "st.async.shared::cluster.mbarrier::complete_tx::bytes.v4.b32 "
        "[%0], {%1, %2, %3, %4}, [%5];"
        :: "r"(raddr),
           "r"(__float_as_uint(a)), "r"(__float_as_uint(b)),
           "r"(__float_as_uint(c)), "r"(__float_as_uint(d)),
           "r"(rbar) : "memory");
}

// MUFU tanh: single-instruction approx (rel err ~5e-4).
__device__ __forceinline__ float tanh_mufu(float x) {
    float y;
    asm("tanh.approx.f32 %0, %1;" : "=f"(y) : "f"(x));
    return y;
}

// ------------------------------ GEMM ---------------------------------------
// out{0,1}[M,N] = A[M,K] @ W{0,1}[N,K]^T + bias{0,1}[N]; z selects direction.
// 128x128 block, BK=8, 256 threads, 8x8 register tile (2x2 blocks of 4x4 at
// +0/+64 split — conflict-free quarter-warp LDS), double-buffered smem.
#define BM 128
#define BN 128
#define BK 8
#define GP 4

__global__ __launch_bounds__(256) void gemm_bias2_kernel(
    const float* __restrict__ X, const int* __restrict__ idx,
    const float* __restrict__ E,
    const float* __restrict__ W0, const float* __restrict__ bias0,
    float* __restrict__ out0,
    const float* __restrict__ W1, const float* __restrict__ bias1,
    float* __restrict__ out1,
    int M, int N, int K)
{
    __shared__ __align__(16) float As[2][BK][BM + GP];
    __shared__ __align__(16) float Bs[2][BK][BN + GP];

    const float* W    = blockIdx.z ? W1    : W0;
    const float* bias = blockIdx.z ? bias1 : bias0;
    float*       out  = blockIdx.z ? out1  : out0;

    int tid  = threadIdx.x;
    int m0   = blockIdx.y * BM, n0 = blockIdx.x * BN;
    int lrow = tid >> 1;            // 0..127
    int lcol = (tid & 1) * 4;       // 0 or 4
    int tx   = tid & 15;            // 0..15
    int ty   = tid >> 4;            // 0..15

    const float* Arow;
    if (idx) Arow = E + (size_t)idx[m0 + lrow] * K;
    else     Arow = X + (size_t)(m0 + lrow) * K;
    const float* Brow = W + (size_t)(n0 + lrow) * K;

    // stage 0
    {
        float4 a = *(const float4*)(Arow + lcol);
        float4 b = *(const float4*)(Brow + lcol);
        As[0][lcol + 0][lrow] = a.x; As[0][lcol + 1][lrow] = a.y;
        As[0][lcol + 2][lrow] = a.z; As[0][lcol + 3][lrow] = a.w;
        Bs[0][lcol + 0][lrow] = b.x; Bs[0][lcol + 1][lrow] = b.y;
        Bs[0][lcol + 2][lrow] = b.z; Bs[0][lcol + 3][lrow] = b.w;
    }
    __syncthreads();

    float acc[8][8] = {};
    int nkb = K / BK;
    int cur = 0;

    for (int kb = 0; kb < nkb; kb++) {
        float4 an, bn;
        bool more = (kb + 1 < nkb);
        if (more) {
            an = *(const float4*)(Arow + (kb + 1) * BK + lcol);
            bn = *(const float4*)(Brow + (kb + 1) * BK + lcol);
        }

        #pragma unroll
        for (int kk = 0; kk < BK; kk++) {
            float4 a0 = *(const float4*)&As[cur][kk][ty * 4];
            float4 a1 = *(const float4*)&As[cur][kk][ty * 4 + 64];
            float4 b0 = *(const float4*)&Bs[cur][kk][tx * 4];
            float4 b1 = *(const float4*)&Bs[cur][kk][tx * 4 + 64];
            float ar[8] = {a0.x, a0.y, a0.z, a0.w, a1.x, a1.y, a1.z, a1.w};
            float br[8] = {b0.x, b0.y, b0.z, b0.w, b1.x, b1.y, b1.z, b1.w};
            #pragma unroll
            for (int i = 0; i < 8; i++)
                #pragma unroll
                for (int j = 0; j < 8; j++)
                    acc[i][j] += ar[i] * br[j];
        }

        if (more) {
            int nxt = cur ^ 1;
            As[nxt][lcol + 0][lrow] = an.x; As[nxt][lcol + 1][lrow] = an.y;
            As[nxt][lcol + 2][lrow] = an.z; As[nxt][lcol + 3][lrow] = an.w;
            Bs[nxt][lcol + 0][lrow] = bn.x; Bs[nxt][lcol + 1][lrow] = bn.y;
            Bs[nxt][lcol + 2][lrow] = bn.z; Bs[nxt][lcol + 3][lrow] = bn.w;
            __syncthreads();
            cur = nxt;
        }
    }

    // epilogue: rows {ty*4+i, ty*4+64+i}, cols {tx*4+j, tx*4+64+j}
    float bv[8];
    #pragma unroll
    for (int j = 0; j < 8; j++)
        bv[j] = bias[n0 + tx * 4 + (j & 3) + (j >> 2) * 64];

    #pragma unroll
    for (int i = 0; i < 8; i++) {
        int m = m0 + ty * 4 + (i & 3) + (i >> 2) * 64;
        float4 r0, r1;
        r0.x = acc[i][0] + bv[0]; r0.y = acc[i][1] + bv[1];
        r0.z = acc[i][2] + bv[2]; r0.w = acc[i][3] + bv[3];
        r1.x = acc[i][4] + bv[4]; r1.y = acc[i][5] + bv[5];
        r1.z = acc[i][6] + bv[6]; r1.w = acc[i][7] + bv[7];
        *(float4*)(out + (size_t)m * N + n0 + tx * 4)      = r0;
        *(float4*)(out + (size_t)m * N + n0 + tx * 4 + 64) = r1;
    }
}

// --------------------------- LSTM recurrence --------------------------------
// Thread map: tid = unit_local*8 + k. Per step: 8 rotated LDS.128, 64 FFMA2,
// width-8 butterfly, lane-split MUFU activation, width-8 gather, cell update.
// h exchange (NEW): warp-aggregated. Each warp covers 4 units; 4 width-32
// shuffles gather the warp's 4 h values into lanes 0..7, and lane r pushes ONE
// st.async.v4.b32 (16B) to CTA r covering the warp's 4-unit slice. Arrivals
// per destination mbarrier: 64 (8 warps x 8 CTAs) instead of 256; total tx
// bytes unchanged (1024) so the expect/wait ring protocol is untouched.
// WAR/ordering proofs carry over: each warp's push depends (via the butterfly
// + gather shuffles) on that warp's reads of hbuf[qp], and any h(t+1) arrival
// transitively requires ALL warps' h(t) pushes.
__global__ void __cluster_dims__(CSZ, 1, 1) __launch_bounds__(256, 1)
lstm_layer_kernel(const float* __restrict__ pre_f, const float* __restrict__ pre_b,
                  const float* __restrict__ Whh_f, const float* __restrict__ Whh_b,
                  float* __restrict__ out, int ostride)
{
    __shared__ __align__(16) float hbuf[2][HID];
    __shared__ __align__(8)  uint64_t mbar_store[4];

    int tid  = threadIdx.x;
    int rank = blockIdx.x & (CSZ - 1);
    int dir  = blockIdx.x / CSZ;

    const float* pre = dir ? pre_b : pre_f;
    const float* Whh = dir ? Whh_b : Whh_f;
    int off = dir ? HID : 0;

    int unit = tid >> 3;                 // 0..31 local unit
    int k    = tid & 7;                  // lane within unit group = K chunk
    int u    = rank * 32 + unit;         // global hidden unit
    int myg  = k & 3;                    // gate this lane activates
    int wl   = tid & 31;                 // lane within warp
    int wrp  = tid >> 5;                 // warp id (covers units 4*wrp..4*wrp+3)

    uint32_t mb_base = smem_u32(&mbar_store[0]);
    uint32_t hb      = smem_u32(&hbuf[0][0]);

    ulonglong2 w2[4][8];
    #pragma unroll
    for (int g = 0; g < 4; g++) {
        const float* wrow = Whh + (size_t)(g * HID + u) * HID + k * 32;
        #pragma unroll
        for (int j = 0; j < 8; j++) {
            int rot = (j + k) & 7;
            w2[g][j] = *(const ulonglong2*)(wrow + rot * 4);
        }
    }

    // push targets: lane r (wl<8, where k==wl) pushes the warp's 4-unit slice
    // [rank*32 + wrp*4, +4) to CTA r. 16B-aligned. r_mbb maps to rank k (==wl
    // for the pushing lanes).
    uint32_t slice_off = (uint32_t)(rank * 32 + wrp * 4) * 4u;
    uint32_t r_h0  = mapa_u32(hb + slice_off, (uint32_t)k);
    uint32_t r_h1  = r_h0 + (uint32_t)HID * 4u;
    uint32_t r_mbb = mapa_u32(mb_base, (uint32_t)k);

    hbuf[0][tid] = 0.f;
    hbuf[1][tid] = 0.f;
    if (tid < 4) mbar_init(mb_base + tid * 8u, 1);
    __syncthreads();
    if (tid == 0) {
        mbar_expect_tx(mb_base + 0u, HID * 4);   // expect h(0)
        mbar_expect_tx(mb_base + 8u, HID * 4);   // expect h(1)
    }
    CLUSTER_SYNC();

    float c = 0.f;
    int tt0 = dir ? (TLEN - 1) : 0;
    float pv = (k < 4) ? __ldg(&pre[tt0 * 1024 + k * HID + u]) : 0.f;

    for (int t = 0; t < TLEN; t++) {
        float pv_next = 0.f;
        if (t + 1 < TLEN && k < 4) {
            int tt1 = dir ? (TLEN - 2 - t) : (t + 1);
            pv_next = __ldg(&pre[tt1 * 1024 + k * HID + u]);
        }

        if (t + 2 < TLEN && tid == 0) {
            mbar_expect_tx(mb_base + (uint32_t)((t + 2) & 3) * 8u, HID * 4);
            asm volatile("fence.proxy.async.shared::cta;" ::: "memory");
        }

        if (t > 0) {
            int tm = t - 1;
            mbar_wait_cluster(mb_base + (uint32_t)(tm & 3) * 8u,
                              (uint32_t)((tm >> 2) & 1));
        }

        int q  = t & 1;
        int qp = q ^ 1;

        const char* hbase = (const char*)&hbuf[qp][k * 32];
        unsigned long long a0[4] = {0ull, 0ull, 0ull, 0ull};
        unsigned long long a1[4] = {0ull, 0ull, 0ull, 0ull};
        #pragma unroll
        for (int j = 0; j < 8; j++) {
            int rot = (j + k) & 7;
            ulonglong2 hv = *(const ulonglong2*)(hbase + rot * 16);
            #pragma unroll
            for (int g = 0; g < 4; g++) {
                asm("fma.rn.f32x2 %0, %1, %2, %0;"
                    : "+l"(a0[g]) : "l"(w2[g][j].x), "l"(hv.x));
                asm("fma.rn.f32x2 %0, %1, %2, %0;"
                    : "+l"(a1[g]) : "l"(w2[g][j].y), "l"(hv.y));
            }
        }
        float s[4];
        #pragma unroll
        for (int g = 0; g < 4; g++) {
            float lo0 = __uint_as_float((unsigned)(a0[g] & 0xffffffffull));
            float hi0 = __uint_as_float((unsigned)(a0[g] >> 32));
            float lo1 = __uint_as_float((unsigned)(a1[g] & 0xffffffffull));
            float hi1 = __uint_as_float((unsigned)(a1[g] >> 32));
            s[g] = (lo0 + hi0) + (lo1 + hi1);
            s[g] += (k == g) ? pv : 0.f;
        }
        #pragma unroll
        for (int m = 1; m < 8; m <<= 1) {
            #pragma unroll
            for (int g = 0; g < 4; g++)
                s[g] += __shfl_xor_sync(0xffffffffu, s[g], m, 8);
        }

        float x   = (myg == 0) ? s[0] : (myg == 1) ? s[1]
                  : (myg == 2) ? s[2] : s[3];
        float z   = (myg == 2) ? x : 0.5f * x;
        float tz  = tanh_mufu(z);
        float act = (myg == 2) ? tz : fmaf(0.5f, tz, 0.5f);

        float ai = __shfl_sync(0xffffffffu, act, 0, 8);
        float af = __shfl_sync(0xffffffffu, act, 1, 8);
        float ag = __shfl_sync(0xffffffffu, act, 2, 8);
        float ao = __shfl_sync(0xffffffffu, act, 3, 8);

        c = af * c + ai * ag;
        float h = ao * tanh_mufu(c);

        int tt = dir ? (TLEN - 1 - t) : t;
        if (k == 0) out[(size_t)tt * ostride + off + u] = h;

        if (t + 1 < TLEN) {
            // warp-aggregate: lane wl gathers h of the warp's 4 units from
            // lanes (wl&7)+8*i; lanes wl<8 push one 16B v4 to CTA wl.
            float h0 = __shfl_sync(0xffffffffu, h, (wl & 7) +  0, 32);
            float h1 = __shfl_sync(0xffffffffu, h, (wl & 7) +  8, 32);
            float h2 = __shfl_sync(0xffffffffu, h, (wl & 7) + 16, 32);
            float h3 = __shfl_sync(0xffffffffu, h, (wl & 7) + 24, 32);
            if (wl < 8) {
                st_async_v4(q ? r_h1 : r_h0, h0, h1, h2, h3,
                            r_mbb + (uint32_t)(t & 3) * 8u);
            }
        }
        pv = pv_next;
    }
}

// ------------------------------ heads --------------------------------------
__global__ __launch_bounds__(256) void heads_kernel(
    const float* __restrict__ x2, const float* __restrict__ Wm,
    float* __restrict__ sh, float* __restrict__ sd)
{
    int warp = threadIdx.x >> 5, lane = threadIdx.x & 31;
    int row = blockIdx.x * 8 + warp;
    const float4* xr = (const float4*)(x2 + (size_t)row * 512);
    const float4* wh = (const float4*)(Wm);
    const float4* wd = (const float4*)(Wm + 512);
    float a = 0.f, b = 0.f;
    #pragma unroll 4
    for (int i = lane; i < 128; i += 32) {
        float4 xv = xr[i]; float4 hv = wh[i]; float4 dv = wd[i];
        a += xv.x * hv.x + xv.y * hv.y + xv.z * hv.z + xv.w * hv.w;
        b += xv.x * dv.x + xv.y * dv.y + xv.z * dv.z + xv.w * dv.w;
    }
    #pragma unroll
    for (int o = 16; o; o >>= 1) {
        a += __shfl_xor_sync(0xffffffffu, a, o);
        b += __shfl_xor_sync(0xffffffffu, b, o);
    }
    if (lane == 0) { sh[row] = a; sd[row] = b; }
}

// ------------------------------ scores -------------------------------------
__global__ __launch_bounds__(256) void scores_kernel(
    const float* __restrict__ sh, const float* __restrict__ sd,
    const float* __restrict__ bm, float* __restrict__ out)
{
    float bb = __ldg(bm);
    size_t nquad = (size_t)TLEN * TLEN / 4;
    size_t stride = (size_t)gridDim.x * blockDim.x;
    for (size_t idx = (size_t)blockIdx.x * blockDim.x + threadIdx.x;
         idx < nquad; idx += stride) {
        int i  = (int)(idx >> 9);           // row (2048/4 = 512 quads per row)
        int j0 = (int)((idx & 511) << 2);   // first col of quad
        float si = sh[i];
        float4 r;
        r.x = (j0 + 0 > i) ? tanh_mufu(si + sd[j0 + 0] + bb) : 0.f;
        r.y = (j0 + 1 > i) ? tanh_mufu(si + sd[j0 + 1] + bb) : 0.f;
        r.z = (j0 + 2 > i) ? tanh_mufu(si + sd[j0 + 2] + bb) : 0.f;
        r.w = (j0 + 3 > i) ? tanh_mufu(si + sd[j0 + 3] + bb) : 0.f;
        *(float4*)(out + ((size_t)i * TLEN + j0)) = r;
    }
}

// ------------------------------ launch -------------------------------------
extern "C" void kernel_launch(void* const* d_in, const int* in_sizes, int n_in,
                              void* d_out, int out_size)
{
    const int*   word_idx = (const int*)  d_in[0];
    const float* E        = (const float*)d_in[1];
    const float* Wih0f    = (const float*)d_in[2];
    const float* Whh0f    = (const float*)d_in[3];
    const float* b0f      = (const float*)d_in[4];
    const float* Wih0b    = (const float*)d_in[5];
    const float* Whh0b    = (const float*)d_in[6];
    const float* b0b      = (const float*)d_in[7];
    const float* Wih1f    = (const float*)d_in[8];
    const float* Whh1f    = (const float*)d_in[9];
    const float* b1f      = (const float*)d_in[10];
    const float* Wih1b    = (const float*)d_in[11];
    const float* Whh1b    = (const float*)d_in[12];
    const float* b1b      = (const float*)d_in[13];
    const float* Wm       = (const float*)d_in[14];
    const float* bm       = (const float*)d_in[15];
    float* out = (float*)d_out;

    float *pre0f, *pre0b, *pre1f, *pre1b, *x1, *x2, *sh, *sd;
    cudaGetSymbolAddress((void**)&pre0f, g_pre0f);
    cudaGetSymbolAddress((void**)&pre0b, g_pre0b);
    cudaGetSymbolAddress((void**)&pre1f, g_pre1f);
    cudaGetSymbolAddress((void**)&pre1b, g_pre1b);
    cudaGetSymbolAddress((void**)&x1,    g_x1);
    cudaGetSymbolAddress((void**)&x2,    g_x2);
    cudaGetSymbolAddress((void**)&sh,    g_sh);
    cudaGetSymbolAddress((void**)&sd,    g_sd);

    dim3 gg(1024 / BN, TLEN / BM, 2);

    // layer 0 input projection (both directions, fused embedding gather)
    gemm_bias2_kernel<<<gg, 256>>>(nullptr, word_idx, E,
                                   Wih0f, b0f, pre0f, Wih0b, b0b, pre0b,
                                   TLEN, 1024, 256);
    // layer 0 recurrence (fwd + bwd clusters)
    lstm_layer_kernel<<<2 * CSZ, 256>>>(pre0f, pre0b, Whh0f, Whh0b, x1, 512);

    // layer 1 input projection
    gemm_bias2_kernel<<<gg, 256>>>(x1, nullptr, nullptr,
                                   Wih1f, b1f, pre1f, Wih1b, b1b, pre1b,
                                   TLEN, 1024, 512);
    // layer 1 recurrence
    lstm_layer_kernel<<<2 * CSZ, 256>>>(pre1f, pre1b, Whh1f, Whh1b, x2, 512);

    // scoring head
    heads_kernel<<<TLEN / 8, 256>>>(x2, Wm, sh, sd);
    scores_kernel<<<2048, 256>>>(sh, sd, bm, out);
}